// round 12
// baseline (speedup 1.0000x reference)
#include <cuda_runtime.h>
#include <cuda_fp16.h>
#include <cstdint>

#define NTOK 2048
#define DDIM 768
#define LDIM 16
#define EPSILON_ 0.3f
#define CEXP (1.0f/(4.0f*EPSILON_))

// ---------------- scratch (no allocations allowed) ----------------
__device__ float g_xproj[NTOK*LDIM];
__device__ float g_sqn[NTOK];
__device__ float g_pi[NTOK];
__device__ __half g_kf16[(size_t)NTOK*NTOK];          // 8.4 MB, K_eps fp16
__device__ float g_qpart[NTOK*32];                    // [i][p] transposed partials
__device__ float g_v[NTOK];
__device__ float g_target[NTOK*DDIM];
__device__ float g_S[NTOK*DDIM];
__device__ __half g_x16[NTOK*DDIM];                   // x fp16
__device__ __half g_fwT16[DDIM*DDIM];                 // f_w^T fp16 : [n, k]
__device__ __half g_tv16[NTOK*DDIM];                  // v[m]*target[m,d] fp16, row-major [m][d]

// ---------------- warp-MMA / cp.async helpers (baseline PTX) ----------
__device__ __forceinline__ uint32_t smem_u32(const void* p) {
    uint32_t a;
    asm("{ .reg .u64 t; cvta.to.shared.u64 t, %1; cvt.u32.u64 %0, t; }" : "=r"(a) : "l"(p));
    return a;
}
__device__ __forceinline__ void ldsm_x4(uint32_t* r, uint32_t addr) {
    asm volatile("ldmatrix.sync.aligned.m8n8.x4.shared.b16 {%0,%1,%2,%3}, [%4];"
        : "=r"(r[0]), "=r"(r[1]), "=r"(r[2]), "=r"(r[3]) : "r"(addr));
}
__device__ __forceinline__ void ldsm_x4_trans(uint32_t* r, uint32_t addr) {
    asm volatile("ldmatrix.sync.aligned.m8n8.x4.trans.shared.b16 {%0,%1,%2,%3}, [%4];"
        : "=r"(r[0]), "=r"(r[1]), "=r"(r[2]), "=r"(r[3]) : "r"(addr));
}
__device__ __forceinline__ void mma16816h(float* c, const uint32_t* a, const uint32_t* b) {
    asm volatile("mma.sync.aligned.m16n8k16.row.col.f32.f16.f16.f32 "
        "{%0,%1,%2,%3}, {%4,%5,%6,%7}, {%8,%9}, {%0,%1,%2,%3};"
        : "+f"(c[0]), "+f"(c[1]), "+f"(c[2]), "+f"(c[3])
        : "r"(a[0]), "r"(a[1]), "r"(a[2]), "r"(a[3]), "r"(b[0]), "r"(b[1]));
}
__device__ __forceinline__ void cp16(uint32_t dst, uint64_t gsrc) {
    asm volatile("cp.async.ca.shared.global [%0], [%1], 16;" :: "r"(dst), "l"(gsrc) : "memory");
}
#define CP_COMMIT() asm volatile("cp.async.commit_group;" ::: "memory")
#define CP_WAIT1()  asm volatile("cp.async.wait_group 1;" ::: "memory")
#define CP_WAIT0()  asm volatile("cp.async.wait_group 0;" ::: "memory")

// ---------------- kernel A: proj/LN/ReLU + pi head + x fp16, UNION f_w^T --------
// blocks [0, 512): proj work, 4 rows each.  blocks [512, 1088): f_w transpose.
__global__ __launch_bounds__(256)
void proj_pi_fw_kernel(const float* __restrict__ x, const float* __restrict__ pw,
                       const float* __restrict__ pb, const float* __restrict__ g1,
                       const float* __restrict__ b1, const float* __restrict__ w1,
                       const float* __restrict__ bb1, const float* __restrict__ w2,
                       const float* __restrict__ bb2, const float* __restrict__ fw)
{
    __shared__ float xs[4][DDIM];
    __shared__ float part[256];
    __shared__ float yv[4][LDIM];
    __shared__ float xp[4][LDIM];
    __shared__ float red[4][8];
    __shared__ float tile[32][33];

    const int t = threadIdx.x;

    if (blockIdx.x >= NTOK/4) {
        // ---- f_w transpose block ----
        const int bid = blockIdx.x - NTOK/4;
        const int bx = bid % (DDIM/32), by = bid / (DDIM/32);
        const int r0 = by*32, c0 = bx*32;
        const int tx = t & 31, ty0 = t >> 5;
        #pragma unroll
        for (int p = 0; p < 4; p++) {
            const int ty = ty0 + p*8;
            tile[ty][tx] = fw[(size_t)(r0+ty)*DDIM + c0+tx];
        }
        __syncthreads();
        #pragma unroll
        for (int p = 0; p < 4; p++) {
            const int ty = ty0 + p*8;
            g_fwT16[(size_t)(c0+ty)*DDIM + r0+tx] = __float2half(tile[tx][ty]);
        }
        return;
    }

    // ---- proj / pi block ----
    const int i0 = blockIdx.x * 4;
    const int lane = t & 31, wid = t >> 5;

    #pragma unroll
    for (int r = 0; r < 4; r++)
        for (int d = t; d < DDIM; d += 256) xs[r][d] = x[(size_t)(i0+r)*DDIM + d];
    __syncthreads();

    #pragma unroll
    for (int r = 0; r < 4; r++)
        for (int d = t; d < DDIM; d += 256)
            g_x16[(size_t)(i0+r)*DDIM + d] = __float2half(xs[r][d]);

    const int l = t & 15, g = t >> 4;
    float accs[4] = {};
    for (int d = g; d < DDIM; d += 16) {
        const float w = pw[d*LDIM + l];
        accs[0] += xs[0][d]*w; accs[1] += xs[1][d]*w;
        accs[2] += xs[2][d]*w; accs[3] += xs[3][d]*w;
    }
    #pragma unroll
    for (int r = 0; r < 4; r++) {
        __syncthreads();
        part[t] = accs[r];
        __syncthreads();
        if (t < LDIM) {
            float s = 0.f;
            #pragma unroll
            for (int gg = 0; gg < 16; gg++) s += part[gg*16 + t];
            yv[r][t] = s + pb[t];
        }
    }
    __syncthreads();
    if (t < 4) {
        float mu = 0.f;
        #pragma unroll
        for (int q = 0; q < LDIM; q++) mu += yv[t][q];
        mu *= (1.f/LDIM);
        float var = 0.f;
        #pragma unroll
        for (int q = 0; q < LDIM; q++) { float dd = yv[t][q]-mu; var += dd*dd; }
        var *= (1.f/LDIM);
        const float is = rsqrtf(var + 1e-5f);
        float sq = 0.f;
        #pragma unroll
        for (int q = 0; q < LDIM; q++) {
            float vv = fmaxf((yv[t][q]-mu)*is*g1[q] + b1[q], 0.f);
            xp[t][q] = vv; sq += vv*vv;
        }
        g_sqn[i0+t] = sq;
    }
    __syncthreads();
    if (t < 64) g_xproj[(i0 + (t>>4))*LDIM + (t&15)] = xp[t>>4][t&15];

    float pacc[4] = {};
    for (int dp = t; dp < DDIM; dp += 256) {
        const float bb = bb1[dp], wo = w2[dp];
        float wc[16];
        #pragma unroll
        for (int q = 0; q < 16; q++) wc[q] = w1[q*DDIM + dp];
        #pragma unroll
        for (int r = 0; r < 4; r++) {
            float h = bb;
            #pragma unroll
            for (int q = 0; q < 16; q++) h += xp[r][q]*wc[q];
            h = fmaxf(h, 0.f);
            pacc[r] += h * wo;
        }
    }
    #pragma unroll
    for (int r = 0; r < 4; r++) {
        float v = pacc[r];
        #pragma unroll
        for (int off = 16; off; off >>= 1) v += __shfl_down_sync(0xffffffffu, v, off);
        if (lane == 0) red[r][wid] = v;
    }
    __syncthreads();
    if (t < 4) {
        float s = 0.f;
        #pragma unroll
        for (int q = 0; q < 8; q++) s += red[t][q];
        g_pi[i0+t] = 1.f/(1.f + __expf(-(s + bb2[0])));
    }
}

// ---------------- kernel B: K_eps tile (64x64) -> fp16 + partial rowsums ----
__global__ __launch_bounds__(256)
void keps_kernel()
{
    const int i0 = blockIdx.y * 64, j0 = blockIdx.x * 64;
    const int t = threadIdx.x;
    const int tx = t & 15, ty = t >> 4;
    __shared__ float xi[64][16];
    __shared__ float xjT[16][64];
    __shared__ float si[64], sj[64];
    __shared__ float rs[64][17];
    {
        const int r = t >> 2, c = (t & 3) * 4;
        float4 a = *(const float4*)&g_xproj[(i0 + r)*LDIM + c];
        *(float4*)&xi[r][c] = a;
        float4 b = *(const float4*)&g_xproj[(j0 + r)*LDIM + c];
        xjT[c+0][r] = b.x; xjT[c+1][r] = b.y; xjT[c+2][r] = b.z; xjT[c+3][r] = b.w;
    }
    if (t < 64) { si[t] = g_sqn[i0+t]; sj[t] = g_sqn[j0+t]; }
    __syncthreads();

    float bj[4][16];
    float sjr[4];
    #pragma unroll
    for (int n = 0; n < 4; n++) {
        const int jj = tx*4 + n;
        sjr[n] = sj[jj];
        #pragma unroll
        for (int q = 0; q < 16; q++) bj[n][q] = xjT[q][jj];
    }
    #pragma unroll
    for (int m = 0; m < 4; m++) {
        const int ii = ty*4 + m;
        float a[16];
        #pragma unroll
        for (int q = 0; q < 16; q++) a[q] = xi[ii][q];
        const float sii = si[ii];
        float o[4]; float rsum = 0.f;
        #pragma unroll
        for (int n = 0; n < 4; n++) {
            float dot = 0.f;
            #pragma unroll
            for (int q = 0; q < 16; q++) dot += a[q]*bj[n][q];
            float kv = __expf(-CEXP*(sii + sjr[n] - 2.f*dot));
            o[n] = kv; rsum += kv;
        }
        const size_t base = (size_t)(i0+ii)*NTOK + j0 + tx*4;
        *(__half2*)&g_kf16[base]   = __floats2half2_rn(o[0], o[1]);
        *(__half2*)&g_kf16[base+2] = __floats2half2_rn(o[2], o[3]);
        rs[ii][tx] = rsum;
    }
    __syncthreads();
    if (t < 64) {
        float s = 0.f;
        #pragma unroll
        for (int c = 0; c < 16; c++) s += rs[t][c];
        g_qpart[(i0 + t)*32 + blockIdx.x] = s;   // transposed: contiguous per row
    }
}

// ---------------- unified fp16 2-stage pipelined GEMM ------------------------
// C[2048,768](f32) = A[2048,K] @ B^T (+bias).  A fp16 K-major [m][k].
// TRANSB=false: B fp16 [n][k] (K-major), non-trans ldmatrix (proven round-7 path).
// TRANSB=true:  B fp16 [k][n] row-major (stride DDIM), trans ldmatrix.
// WRITE_TV: compute v from qpart/pi, also emit g_tv16[m][d]=half(v[m]*C[m][d]).
// BM=128 BN=64 BK=32, 8 warps (4 M x 2 N), warp tile 32x32, double-buffered.
#define GROWB 80                 // A: bytes per padded row (32 k * 2B -> 80)
#define BROWB_T 144              // TRANSB B: bytes per padded row (64 n * 2B -> 144)
#define GSTG_B0 10240            // A region = 128*80
template<bool ADD_BIAS, bool TRANSB, bool WRITE_TV>
__device__ __forceinline__
void gemm16_body(const __half* __restrict__ A, const __half* __restrict__ B,
                 const float* __restrict__ bias, float* __restrict__ C, int K)
{
    constexpr uint32_t STG = TRANSB ? (GSTG_B0 + 32*BROWB_T)   // 14848
                                    : (GSTG_B0 + 64*GROWB);    // 15360
    __shared__ __align__(16) char smem_raw[2*STG];
    __shared__ float vsm[128];
    const uint32_t sbase = smem_u32(smem_raw);
    const int tid = threadIdx.x;
    const int lane = tid & 31, w = tid >> 5;
    const int wm = w >> 1, wn = w & 1;
    const int m0 = blockIdx.y * 128, n0 = blockIdx.x * 64;

    // per-thread cp.async assignments: 768 x 16B per chunk, 3 per thread
    uint64_t srcs[3]; uint32_t dsts[3]; uint64_t advs[3];
    #pragma unroll
    for (int it = 0; it < 3; it++) {
        const int idx = tid + it*256;
        if (idx < 512) {
            const int r = idx >> 2, q = idx & 3;
            srcs[it] = (uint64_t)__cvta_generic_to_global(A + (size_t)(m0+r)*K + q*8);
            dsts[it] = r*GROWB + q*16;
            advs[it] = 64;                              // 32 k * 2B
        } else if (!TRANSB) {
            const int j = idx - 512;
            const int r = j >> 2, q = j & 3;
            srcs[it] = (uint64_t)__cvta_generic_to_global(B + (size_t)(n0+r)*K + q*8);
            dsts[it] = GSTG_B0 + r*GROWB + q*16;
            advs[it] = 64;
        } else {
            const int j = idx - 512;                    // 0..255
            const int r = j >> 3, q = j & 7;            // r: 32 k-rows, q: 8 x 16B over 64 n
            srcs[it] = (uint64_t)__cvta_generic_to_global(B + (size_t)r*DDIM + n0 + q*8);
            dsts[it] = GSTG_B0 + r*BROWB_T + q*16;
            advs[it] = (uint64_t)32*DDIM*2;             // advance 32 k-rows
        }
    }

    // A-fragment ldmatrix offsets (bytes, within stage)
    const uint32_t aRow = wm*32 + (lane & 7) + ((lane >> 3) & 1)*8;
    const uint32_t aCol = ((lane >> 4) & 1)*8;
    uint32_t aOff[2];
    #pragma unroll
    for (int mt = 0; mt < 2; mt++) aOff[mt] = (aRow + mt*16)*GROWB + aCol*2;

    // B-fragment ldmatrix offsets
    uint32_t bOff[2];
    if (!TRANSB) {
        const uint32_t bRowBase = wn*32 + ((lane >> 4) & 1)*8 + (lane & 7);
        const uint32_t bCol = ((lane >> 3) & 1)*8;
        #pragma unroll
        for (int np = 0; np < 2; np++)
            bOff[np] = GSTG_B0 + (bRowBase + np*16)*GROWB + bCol*2;
    } else {
        const uint32_t kRow = (lane & 7) + ((lane >> 3) & 1)*8;
        #pragma unroll
        for (int np = 0; np < 2; np++) {
            const uint32_t nCol = wn*32 + np*16 + ((lane >> 4) & 1)*8;
            bOff[np] = GSTG_B0 + kRow*BROWB_T + nCol*2;
        }
    }

    float acc[2][2][2][4] = {};   // [mt][np][j][4]

    // prologue: chunk 0 -> stage 0
    #pragma unroll
    for (int it = 0; it < 3; it++) cp16(sbase + dsts[it], srcs[it]);
    CP_COMMIT();

    // overlap: compute v for this CTA's 128 rows while chunk 0 is in flight
    if (WRITE_TV) {
        #pragma unroll
        for (int i = 0; i < 16; i++) {
            const int r = w*16 + i;
            float q = g_qpart[(m0 + r)*32 + lane];
            #pragma unroll
            for (int off = 16; off; off >>= 1) q += __shfl_xor_sync(0xffffffffu, q, off);
            if (lane == 0) {
                const float vv = g_pi[m0 + r] / q;
                vsm[r] = vv;
                if (blockIdx.x == 0) g_v[m0 + r] = vv;
            }
        }
    }

    const int nch = K >> 5;
    for (int c = 0; c < nch; c++) {
        const uint32_t so = sbase + (uint32_t)(c & 1)*STG;
        if (c + 1 < nch) {
            const uint32_t sn = sbase + (uint32_t)((c+1) & 1)*STG;
            #pragma unroll
            for (int it = 0; it < 3; it++)
                cp16(sn + dsts[it], srcs[it] + (uint64_t)(c+1)*advs[it]);
            CP_COMMIT();
            CP_WAIT1();
        } else {
            CP_WAIT0();
        }
        __syncthreads();

        #pragma unroll
        for (int kk = 0; kk < 2; kk++) {
            uint32_t Af[2][4], Bf[2][4];
            ldsm_x4(Af[0], so + aOff[0] + kk*32);
            ldsm_x4(Af[1], so + aOff[1] + kk*32);
            if (!TRANSB) {
                ldsm_x4(Bf[0], so + bOff[0] + kk*32);
                ldsm_x4(Bf[1], so + bOff[1] + kk*32);
            } else {
                ldsm_x4_trans(Bf[0], so + bOff[0] + kk*16*BROWB_T);
                ldsm_x4_trans(Bf[1], so + bOff[1] + kk*16*BROWB_T);
            }
            #pragma unroll
            for (int mt = 0; mt < 2; mt++)
                #pragma unroll
                for (int np = 0; np < 2; np++) {
                    mma16816h(acc[mt][np][0], Af[mt], &Bf[np][0]);
                    mma16816h(acc[mt][np][1], Af[mt], &Bf[np][2]);
                }
        }
        __syncthreads();
    }

    const int g = lane >> 2, tg2 = (lane & 3)*2;
    #pragma unroll
    for (int mt = 0; mt < 2; mt++) {
        const int r0 = wm*32 + mt*16 + g;
        const int row = m0 + r0;
        float s0 = 0.f, s1 = 0.f;
        if (WRITE_TV) { s0 = vsm[r0]; s1 = vsm[r0 + 8]; }
        #pragma unroll
        for (int np = 0; np < 2; np++)
            #pragma unroll
            for (int j = 0; j < 2; j++) {
                const int col = n0 + wn*32 + np*16 + j*8 + tg2;
                float b0 = 0.f, b1 = 0.f;
                if (ADD_BIAS) { b0 = bias[col]; b1 = bias[col+1]; }
                const float* cc = acc[mt][np][j];
                const float v00 = cc[0]+b0, v01 = cc[1]+b1;
                const float v10 = cc[2]+b0, v11 = cc[3]+b1;
                *(float2*)&C[(size_t)row*DDIM + col] = make_float2(v00, v01);
                *(float2*)&C[(size_t)(row+8)*DDIM + col] = make_float2(v10, v11);
                if (WRITE_TV) {
                    *(__half2*)&g_tv16[(size_t)row*DDIM + col] =
                        __floats2half2_rn(v00*s0, v01*s0);
                    *(__half2*)&g_tv16[(size_t)(row+8)*DDIM + col] =
                        __floats2half2_rn(v10*s1, v11*s1);
                }
            }
    }
}

__global__ __launch_bounds__(256)
void gemm_target_kernel(const float* __restrict__ fb)
{
    gemm16_body<true, false, true>(g_x16, g_fwT16, fb, g_target, DDIM);
}
__global__ __launch_bounds__(256)
void gemm_S_kernel()
{
    gemm16_body<false, true, false>(g_kf16, g_tv16, nullptr, g_S, NTOK);
}

// ---------------- final: d_i + combine + LayerNorm(768) ----------------
__global__ __launch_bounds__(256)
void final_kernel(const float* __restrict__ x, const float* __restrict__ dtp,
                  const float* __restrict__ g2, const float* __restrict__ b2,
                  float* __restrict__ out)
{
    const int i = blockIdx.x;
    const int t = threadIdx.x;
    __shared__ float rsm[256], rqm[256];
    __shared__ float invd_s, mu_s, is_s;

    // fused dvec: d_i = K_eps[i,:] . v + 1e-5
    {
        const __half2* krow = (const __half2*)&g_kf16[(size_t)i*NTOK];
        const int h = t*4;
        __half2 k0 = krow[h], k1 = krow[h+1], k2 = krow[h+2], k3 = krow[h+3];
        float4 v0 = *(const float4*)&g_v[t*8];
        float4 v1 = *(const float4*)&g_v[t*8+4];
        float2 f0 = __half22float2(k0), f1 = __half22float2(k1);
        float2 f2 = __half22float2(k2), f3 = __half22float2(k3);
        rsm[t] = f0.x*v0.x + f0.y*v0.y + f1.x*v0.z + f1.y*v0.w
               + f2.x*v1.x + f2.y*v1.y + f3.x*v1.z + f3.y*v1.w;
    }
    __syncthreads();
    for (int s = 128; s > 0; s >>= 1) {
        if (t < s) rsm[t] += rsm[t+s];
        __syncthreads();
    }
    if (t == 0) invd_s = (1.f/EPSILON_) / (rsm[0] + 1e-5f);
    __syncthreads();

    const float dtv = dtp[0];
    const float invd = invd_s;

    float vals[3];
    float sum = 0.f, sq = 0.f;
    #pragma unroll
    for (int c = 0; c < 3; c++) {
        const int d = t + c*256;
        const float tg = g_target[(size_t)i*DDIM + d];
        const float tt = dtv * (invd * g_S[(size_t)i*DDIM + d] - tg);
        const float t2 = 0.7f * x[(size_t)i*DDIM + d] + 0.3f*(tg + 2.f*tt);
        vals[c] = t2; sum += t2; sq += t2*t2;
    }
    __syncthreads();
    rsm[t] = sum; rqm[t] = sq;
    __syncthreads();
    for (int s = 128; s > 0; s >>= 1) {
        if (t < s) { rsm[t] += rsm[t+s]; rqm[t] += rqm[t+s]; }
        __syncthreads();
    }
    if (t == 0) {
        float mu = rsm[0] * (1.f/DDIM);
        float var = rqm[0] * (1.f/DDIM) - mu*mu;
        mu_s = mu; is_s = rsqrtf(var + 1e-5f);
    }
    __syncthreads();
    #pragma unroll
    for (int c = 0; c < 3; c++) {
        const int d = t + c*256;
        out[(size_t)i*DDIM + d] = (vals[c]-mu_s)*is_s*g2[d] + b2[d];
    }
}

// ---------------- launch (pure kernel launches; nothing else) ----------------
extern "C" void kernel_launch(void* const* d_in, const int* in_sizes, int n_in,
                              void* d_out, int out_size)
{
    const float* x      = (const float*)d_in[0];
    const float* proj_w = (const float*)d_in[1];
    const float* proj_b = (const float*)d_in[2];
    const float* ln1_g  = (const float*)d_in[3];
    const float* ln1_b  = (const float*)d_in[4];
    const float* pi_w1  = (const float*)d_in[5];
    const float* pi_b1  = (const float*)d_in[6];
    const float* pi_w2  = (const float*)d_in[7];
    const float* pi_b2  = (const float*)d_in[8];
    const float* dt     = (const float*)d_in[9];
    const float* f_w    = (const float*)d_in[10];
    const float* f_b    = (const float*)d_in[11];
    const float* ln2_g  = (const float*)d_in[12];
    const float* ln2_b  = (const float*)d_in[13];
    float* out = (float*)d_out;

    proj_pi_fw_kernel<<<NTOK/4 + (DDIM/32)*(DDIM/32), 256>>>(
        x, proj_w, proj_b, ln1_g, ln1_b, pi_w1, pi_b1, pi_w2, pi_b2, f_w);
    keps_kernel<<<dim3(32,32), 256>>>();
    gemm_target_kernel<<<dim3(DDIM/64, NTOK/128), 256>>>(f_b);
    gemm_S_kernel<<<dim3(DDIM/64, NTOK/128), 256>>>();
    final_kernel<<<NTOK, 256>>>(x, dt, ln2_g, ln2_b, out);
}

// round 14
// speedup vs baseline: 1.0591x; 1.0591x over previous
#include <cuda_runtime.h>
#include <cuda_fp16.h>
#include <cstdint>

#define NTOK 2048
#define DDIM 768
#define LDIM 16
#define EPSILON_ 0.3f
#define CEXP (1.0f/(4.0f*EPSILON_))

// ---------------- scratch (no allocations allowed) ----------------
__device__ float g_xproj[NTOK*LDIM];
__device__ float g_sqn[NTOK];
__device__ float g_pi[NTOK];
__device__ __half g_kf16[(size_t)NTOK*NTOK];          // 8.4 MB, K_eps fp16
__device__ float g_qpart[NTOK*32];                    // [i][p] transposed partials
__device__ float g_v[NTOK];
__device__ float g_target[NTOK*DDIM];
__device__ float g_S[NTOK*DDIM];
__device__ __half g_x16[NTOK*DDIM];                   // x fp16
__device__ __half g_fwT16[DDIM*DDIM];                 // f_w^T fp16 : [n, k]
__device__ __half g_tv16[NTOK*DDIM];                  // v[m]*target[m,d] fp16, row-major [m][d]

// ---------------- warp-MMA / cp.async helpers (baseline PTX) ----------
__device__ __forceinline__ uint32_t smem_u32(const void* p) {
    uint32_t a;
    asm("{ .reg .u64 t; cvta.to.shared.u64 t, %1; cvt.u32.u64 %0, t; }" : "=r"(a) : "l"(p));
    return a;
}
__device__ __forceinline__ void ldsm_x4(uint32_t* r, uint32_t addr) {
    asm volatile("ldmatrix.sync.aligned.m8n8.x4.shared.b16 {%0,%1,%2,%3}, [%4];"
        : "=r"(r[0]), "=r"(r[1]), "=r"(r[2]), "=r"(r[3]) : "r"(addr));
}
__device__ __forceinline__ void ldsm_x4_trans(uint32_t* r, uint32_t addr) {
    asm volatile("ldmatrix.sync.aligned.m8n8.x4.trans.shared.b16 {%0,%1,%2,%3}, [%4];"
        : "=r"(r[0]), "=r"(r[1]), "=r"(r[2]), "=r"(r[3]) : "r"(addr));
}
__device__ __forceinline__ void mma16816h(float* c, const uint32_t* a, const uint32_t* b) {
    asm volatile("mma.sync.aligned.m16n8k16.row.col.f32.f16.f16.f32 "
        "{%0,%1,%2,%3}, {%4,%5,%6,%7}, {%8,%9}, {%0,%1,%2,%3};"
        : "+f"(c[0]), "+f"(c[1]), "+f"(c[2]), "+f"(c[3])
        : "r"(a[0]), "r"(a[1]), "r"(a[2]), "r"(a[3]), "r"(b[0]), "r"(b[1]));
}
__device__ __forceinline__ void cp16(uint32_t dst, uint64_t gsrc) {
    asm volatile("cp.async.ca.shared.global [%0], [%1], 16;" :: "r"(dst), "l"(gsrc) : "memory");
}
#define CP_COMMIT() asm volatile("cp.async.commit_group;" ::: "memory")
#define CP_WAIT1()  asm volatile("cp.async.wait_group 1;" ::: "memory")
#define CP_WAIT0()  asm volatile("cp.async.wait_group 0;" ::: "memory")

// ---------------- kernel A: proj/LN/ReLU + pi head + x fp16, UNION f_w^T --------
// blocks [0, 512): proj work, 4 rows each.  blocks [512, 1088): f_w transpose.
__global__ __launch_bounds__(256)
void proj_pi_fw_kernel(const float* __restrict__ x, const float* __restrict__ pw,
                       const float* __restrict__ pb, const float* __restrict__ g1,
                       const float* __restrict__ b1, const float* __restrict__ w1,
                       const float* __restrict__ bb1, const float* __restrict__ w2,
                       const float* __restrict__ bb2, const float* __restrict__ fw)
{
    __shared__ float xs[4][DDIM];
    __shared__ float part[256];
    __shared__ float yv[4][LDIM];
    __shared__ float xp[4][LDIM];
    __shared__ float red[4][8];
    __shared__ float tile[32][33];

    const int t = threadIdx.x;

    if (blockIdx.x >= NTOK/4) {
        // ---- f_w transpose block ----
        const int bid = blockIdx.x - NTOK/4;
        const int bx = bid % (DDIM/32), by = bid / (DDIM/32);
        const int r0 = by*32, c0 = bx*32;
        const int tx = t & 31, ty0 = t >> 5;
        #pragma unroll
        for (int p = 0; p < 4; p++) {
            const int ty = ty0 + p*8;
            tile[ty][tx] = fw[(size_t)(r0+ty)*DDIM + c0+tx];
        }
        __syncthreads();
        #pragma unroll
        for (int p = 0; p < 4; p++) {
            const int ty = ty0 + p*8;
            g_fwT16[(size_t)(c0+ty)*DDIM + r0+tx] = __float2half(tile[tx][ty]);
        }
        return;
    }

    // ---- proj / pi block ----
    const int i0 = blockIdx.x * 4;
    const int lane = t & 31, wid = t >> 5;

    #pragma unroll
    for (int r = 0; r < 4; r++)
        for (int d = t; d < DDIM; d += 256) xs[r][d] = x[(size_t)(i0+r)*DDIM + d];
    __syncthreads();

    #pragma unroll
    for (int r = 0; r < 4; r++)
        for (int d = t; d < DDIM; d += 256)
            g_x16[(size_t)(i0+r)*DDIM + d] = __float2half(xs[r][d]);

    const int l = t & 15, g = t >> 4;
    float accs[4] = {};
    for (int d = g; d < DDIM; d += 16) {
        const float w = pw[d*LDIM + l];
        accs[0] += xs[0][d]*w; accs[1] += xs[1][d]*w;
        accs[2] += xs[2][d]*w; accs[3] += xs[3][d]*w;
    }
    #pragma unroll
    for (int r = 0; r < 4; r++) {
        __syncthreads();
        part[t] = accs[r];
        __syncthreads();
        if (t < LDIM) {
            float s = 0.f;
            #pragma unroll
            for (int gg = 0; gg < 16; gg++) s += part[gg*16 + t];
            yv[r][t] = s + pb[t];
        }
    }
    __syncthreads();
    if (t < 4) {
        float mu = 0.f;
        #pragma unroll
        for (int q = 0; q < LDIM; q++) mu += yv[t][q];
        mu *= (1.f/LDIM);
        float var = 0.f;
        #pragma unroll
        for (int q = 0; q < LDIM; q++) { float dd = yv[t][q]-mu; var += dd*dd; }
        var *= (1.f/LDIM);
        const float is = rsqrtf(var + 1e-5f);
        float sq = 0.f;
        #pragma unroll
        for (int q = 0; q < LDIM; q++) {
            float vv = fmaxf((yv[t][q]-mu)*is*g1[q] + b1[q], 0.f);
            xp[t][q] = vv; sq += vv*vv;
        }
        g_sqn[i0+t] = sq;
    }
    __syncthreads();
    if (t < 64) g_xproj[(i0 + (t>>4))*LDIM + (t&15)] = xp[t>>4][t&15];

    float pacc[4] = {};
    for (int dp = t; dp < DDIM; dp += 256) {
        const float bb = bb1[dp], wo = w2[dp];
        float wc[16];
        #pragma unroll
        for (int q = 0; q < 16; q++) wc[q] = w1[q*DDIM + dp];
        #pragma unroll
        for (int r = 0; r < 4; r++) {
            float h = bb;
            #pragma unroll
            for (int q = 0; q < 16; q++) h += xp[r][q]*wc[q];
            h = fmaxf(h, 0.f);
            pacc[r] += h * wo;
        }
    }
    #pragma unroll
    for (int r = 0; r < 4; r++) {
        float v = pacc[r];
        #pragma unroll
        for (int off = 16; off; off >>= 1) v += __shfl_down_sync(0xffffffffu, v, off);
        if (lane == 0) red[r][wid] = v;
    }
    __syncthreads();
    if (t < 4) {
        float s = 0.f;
        #pragma unroll
        for (int q = 0; q < 8; q++) s += red[t][q];
        g_pi[i0+t] = 1.f/(1.f + __expf(-(s + bb2[0])));
    }
}

// ---------------- kernel B: K_eps tile (64x64) -> fp16 + partial rowsums ----
__global__ __launch_bounds__(256)
void keps_kernel()
{
    const int i0 = blockIdx.y * 64, j0 = blockIdx.x * 64;
    const int t = threadIdx.x;
    const int tx = t & 15, ty = t >> 4;
    __shared__ float xi[64][16];
    __shared__ float xjT[16][64];
    __shared__ float si[64], sj[64];
    __shared__ float rs[64][17];
    {
        const int r = t >> 2, c = (t & 3) * 4;
        float4 a = *(const float4*)&g_xproj[(i0 + r)*LDIM + c];
        *(float4*)&xi[r][c] = a;
        float4 b = *(const float4*)&g_xproj[(j0 + r)*LDIM + c];
        xjT[c+0][r] = b.x; xjT[c+1][r] = b.y; xjT[c+2][r] = b.z; xjT[c+3][r] = b.w;
    }
    if (t < 64) { si[t] = g_sqn[i0+t]; sj[t] = g_sqn[j0+t]; }
    __syncthreads();

    float bj[4][16];
    float sjr[4];
    #pragma unroll
    for (int n = 0; n < 4; n++) {
        const int jj = tx*4 + n;
        sjr[n] = sj[jj];
        #pragma unroll
        for (int q = 0; q < 16; q++) bj[n][q] = xjT[q][jj];
    }
    #pragma unroll
    for (int m = 0; m < 4; m++) {
        const int ii = ty*4 + m;
        float a[16];
        #pragma unroll
        for (int q = 0; q < 16; q++) a[q] = xi[ii][q];
        const float sii = si[ii];
        float o[4]; float rsum = 0.f;
        #pragma unroll
        for (int n = 0; n < 4; n++) {
            float dot = 0.f;
            #pragma unroll
            for (int q = 0; q < 16; q++) dot += a[q]*bj[n][q];
            float kv = __expf(-CEXP*(sii + sjr[n] - 2.f*dot));
            o[n] = kv; rsum += kv;
        }
        const size_t base = (size_t)(i0+ii)*NTOK + j0 + tx*4;
        *(__half2*)&g_kf16[base]   = __floats2half2_rn(o[0], o[1]);
        *(__half2*)&g_kf16[base+2] = __floats2half2_rn(o[2], o[3]);
        rs[ii][tx] = rsum;
    }
    __syncthreads();
    if (t < 64) {
        float s = 0.f;
        #pragma unroll
        for (int c = 0; c < 16; c++) s += rs[t][c];
        g_qpart[(i0 + t)*32 + blockIdx.x] = s;   // transposed: contiguous per row
    }
}

// ---------------- unified fp16 2-stage pipelined GEMM, BM=64 ------------------
// C[2048,768](f32) = A[2048,K] @ B^T (+bias).  A fp16 K-major [m][k].
// TRANSB=false: B fp16 [n][k] (K-major), non-trans ldmatrix.
// TRANSB=true:  B fp16 [k][n] row-major (stride DDIM), trans ldmatrix.
// WRITE_TV: compute v from qpart/pi, also emit g_tv16[m][d]=half(v[m]*C[m][d]).
// BM=64 BN=64 BK=32, 8 warps (2 M x 4 N), warp tile 32x16, double-buffered.
#define GROWB 80                 // bytes per padded A/B(nk) row (32 k * 2B -> 80)
#define BROWB_T 144              // TRANSB B: bytes per padded row (64 n * 2B -> 144)
#define ASTG 5120                // A region = 64*80
template<bool ADD_BIAS, bool TRANSB, bool WRITE_TV>
__device__ __forceinline__
void gemm16_body(const __half* __restrict__ A, const __half* __restrict__ B,
                 const float* __restrict__ bias, float* __restrict__ C, int K)
{
    constexpr uint32_t STG = TRANSB ? (ASTG + 32*BROWB_T)   // 9728
                                    : (ASTG + 64*GROWB);    // 10240
    __shared__ __align__(16) char smem_raw[2*STG];          // <= 20 KB
    __shared__ float vsm[64];
    const uint32_t sbase = smem_u32(smem_raw);
    const int tid = threadIdx.x;
    const int lane = tid & 31, w = tid >> 5;
    const int wm = w & 1, wn = w >> 1;
    const int m0 = blockIdx.y * 64, n0 = blockIdx.x * 64;

    // per-thread cp.async assignments: 512 x 16B per chunk, 2 per thread
    uint64_t srcs[2]; uint32_t dsts[2]; uint64_t advs[2];
    #pragma unroll
    for (int it = 0; it < 2; it++) {
        const int idx = tid + it*256;
        if (idx < 256) {
            const int r = idx >> 2, q = idx & 3;            // 64 rows x 4 x 16B
            srcs[it] = (uint64_t)__cvta_generic_to_global(A + (size_t)(m0+r)*K + q*8);
            dsts[it] = r*GROWB + q*16;
            advs[it] = 64;                                   // 32 k * 2B
        } else if (!TRANSB) {
            const int j = idx - 256;
            const int r = j >> 2, q = j & 3;                 // 64 rows x 4 x 16B
            srcs[it] = (uint64_t)__cvta_generic_to_global(B + (size_t)(n0+r)*K + q*8);
            dsts[it] = ASTG + r*GROWB + q*16;
            advs[it] = 64;
        } else {
            const int j = idx - 256;                         // 0..255
            const int r = j >> 3, q = j & 7;                 // 32 k-rows x 8 x 16B
            srcs[it] = (uint64_t)__cvta_generic_to_global(B + (size_t)r*DDIM + n0 + q*8);
            dsts[it] = ASTG + r*BROWB_T + q*16;
            advs[it] = (uint64_t)32*DDIM*2;                  // advance 32 k-rows
        }
    }

    // A-fragment ldmatrix offsets (bytes, within stage)
    const uint32_t aRow = wm*32 + (lane & 7) + ((lane >> 3) & 1)*8;
    const uint32_t aCol = ((lane >> 4) & 1)*8;
    uint32_t aOff[2];
    #pragma unroll
    for (int mt = 0; mt < 2; mt++) aOff[mt] = (aRow + mt*16)*GROWB + aCol*2;

    // B-fragment ldmatrix offset (warp tile n = 16 -> single x4)
    uint32_t bOff;
    if (!TRANSB) {
        const uint32_t bRow = wn*16 + ((lane >> 4) & 1)*8 + (lane & 7);
        const uint32_t bCol = ((lane >> 3) & 1)*8;
        bOff = ASTG + bRow*GROWB + bCol*2;
    } else {
        const uint32_t kRow = (lane & 7) + ((lane >> 3) & 1)*8;
        const uint32_t nCol = wn*16 + ((lane >> 4) & 1)*8;
        bOff = ASTG + kRow*BROWB_T + nCol*2;
    }

    float acc[2][2][4] = {};   // [mt][j][4]

    // prologue: chunk 0 -> stage 0
    #pragma unroll
    for (int it = 0; it < 2; it++) cp16(sbase + dsts[it], srcs[it]);
    CP_COMMIT();

    // overlap: compute v for this CTA's 64 rows while chunk 0 is in flight
    if (WRITE_TV) {
        #pragma unroll
        for (int i = 0; i < 8; i++) {
            const int r = w*8 + i;
            float q = g_qpart[(m0 + r)*32 + lane];
            #pragma unroll
            for (int off = 16; off; off >>= 1) q += __shfl_xor_sync(0xffffffffu, q, off);
            if (lane == 0) {
                const float vv = g_pi[m0 + r] / q;
                vsm[r] = vv;
                if (blockIdx.x == 0) g_v[m0 + r] = vv;
            }
        }
    }

    const int nch = K >> 5;
    for (int c = 0; c < nch; c++) {
        const uint32_t so = sbase + (uint32_t)(c & 1)*STG;
        if (c + 1 < nch) {
            const uint32_t sn = sbase + (uint32_t)((c+1) & 1)*STG;
            #pragma unroll
            for (int it = 0; it < 2; it++)
                cp16(sn + dsts[it], srcs[it] + (uint64_t)(c+1)*advs[it]);
            CP_COMMIT();
            CP_WAIT1();
        } else {
            CP_WAIT0();
        }
        __syncthreads();

        #pragma unroll
        for (int kk = 0; kk < 2; kk++) {
            uint32_t Af[2][4], Bf[4];
            ldsm_x4(Af[0], so + aOff[0] + kk*32);
            ldsm_x4(Af[1], so + aOff[1] + kk*32);
            if (!TRANSB) ldsm_x4(Bf, so + bOff + kk*32);
            else         ldsm_x4_trans(Bf, so + bOff + kk*16*BROWB_T);
            #pragma unroll
            for (int mt = 0; mt < 2; mt++) {
                mma16816h(acc[mt][0], Af[mt], &Bf[0]);
                mma16816h(acc[mt][1], Af[mt], &Bf[2]);
            }
        }
        __syncthreads();
    }

    const int g = lane >> 2, tg2 = (lane & 3)*2;
    #pragma unroll
    for (int mt = 0; mt < 2; mt++) {
        const int r0 = wm*32 + mt*16 + g;
        const int row = m0 + r0;
        float s0 = 0.f, s1 = 0.f;
        if (WRITE_TV) { s0 = vsm[r0]; s1 = vsm[r0 + 8]; }
        #pragma unroll
        for (int j = 0; j < 2; j++) {
            const int col = n0 + wn*16 + j*8 + tg2;
            float b0 = 0.f, b1 = 0.f;
            if (ADD_BIAS) { b0 = bias[col]; b1 = bias[col+1]; }
            const float* cc = acc[mt][j];
            const float v00 = cc[0]+b0, v01 = cc[1]+b1;
            const float v10 = cc[2]+b0, v11 = cc[3]+b1;
            *(float2*)&C[(size_t)row*DDIM + col] = make_float2(v00, v01);
            *(float2*)&C[(size_t)(row+8)*DDIM + col] = make_float2(v10, v11);
            if (WRITE_TV) {
                *(__half2*)&g_tv16[(size_t)row*DDIM + col] =
                    __floats2half2_rn(v00*s0, v01*s0);
                *(__half2*)&g_tv16[(size_t)(row+8)*DDIM + col] =
                    __floats2half2_rn(v10*s1, v11*s1);
            }
        }
    }
}

__global__ __launch_bounds__(256)
void gemm_target_kernel(const float* __restrict__ fb)
{
    gemm16_body<true, false, true>(g_x16, g_fwT16, fb, g_target, DDIM);
}
__global__ __launch_bounds__(256)
void gemm_S_kernel()
{
    gemm16_body<false, true, false>(g_kf16, g_tv16, nullptr, g_S, NTOK);
}

// ---------------- final: d_i + combine + LayerNorm(768) ----------------
__global__ __launch_bounds__(256)
void final_kernel(const float* __restrict__ x, const float* __restrict__ dtp,
                  const float* __restrict__ g2, const float* __restrict__ b2,
                  float* __restrict__ out)
{
    const int i = blockIdx.x;
    const int t = threadIdx.x;
    __shared__ float rsm[256], rqm[256];
    __shared__ float invd_s, mu_s, is_s;

    // fused dvec: d_i = K_eps[i,:] . v + 1e-5
    {
        const __half2* krow = (const __half2*)&g_kf16[(size_t)i*NTOK];
        const int h = t*4;
        __half2 k0 = krow[h], k1 = krow[h+1], k2 = krow[h+2], k3 = krow[h+3];
        float4 v0 = *(const float4*)&g_v[t*8];
        float4 v1 = *(const float4*)&g_v[t*8+4];
        float2 f0 = __half22float2(k0), f1 = __half22float2(k1);
        float2 f2 = __half22float2(k2), f3 = __half22float2(k3);
        rsm[t] = f0.x*v0.x + f0.y*v0.y + f1.x*v0.z + f1.y*v0.w
               + f2.x*v1.x + f2.y*v1.y + f3.x*v1.z + f3.y*v1.w;
    }
    __syncthreads();
    for (int s = 128; s > 0; s >>= 1) {
        if (t < s) rsm[t] += rsm[t+s];
        __syncthreads();
    }
    if (t == 0) invd_s = (1.f/EPSILON_) / (rsm[0] + 1e-5f);
    __syncthreads();

    const float dtv = dtp[0];
    const float invd = invd_s;

    float vals[3];
    float sum = 0.f, sq = 0.f;
    #pragma unroll
    for (int c = 0; c < 3; c++) {
        const int d = t + c*256;
        const float tg = g_target[(size_t)i*DDIM + d];
        const float tt = dtv * (invd * g_S[(size_t)i*DDIM + d] - tg);
        const float t2 = 0.7f * x[(size_t)i*DDIM + d] + 0.3f*(tg + 2.f*tt);
        vals[c] = t2; sum += t2; sq += t2*t2;
    }
    __syncthreads();
    rsm[t] = sum; rqm[t] = sq;
    __syncthreads();
    for (int s = 128; s > 0; s >>= 1) {
        if (t < s) { rsm[t] += rsm[t+s]; rqm[t] += rqm[t+s]; }
        __syncthreads();
    }
    if (t == 0) {
        float mu = rsm[0] * (1.f/DDIM);
        float var = rqm[0] * (1.f/DDIM) - mu*mu;
        mu_s = mu; is_s = rsqrtf(var + 1e-5f);
    }
    __syncthreads();
    #pragma unroll
    for (int c = 0; c < 3; c++) {
        const int d = t + c*256;
        out[(size_t)i*DDIM + d] = (vals[c]-mu_s)*is_s*g2[d] + b2[d];
    }
}

// ---------------- launch (pure kernel launches; nothing else) ----------------
extern "C" void kernel_launch(void* const* d_in, const int* in_sizes, int n_in,
                              void* d_out, int out_size)
{
    const float* x      = (const float*)d_in[0];
    const float* proj_w = (const float*)d_in[1];
    const float* proj_b = (const float*)d_in[2];
    const float* ln1_g  = (const float*)d_in[3];
    const float* ln1_b  = (const float*)d_in[4];
    const float* pi_w1  = (const float*)d_in[5];
    const float* pi_b1  = (const float*)d_in[6];
    const float* pi_w2  = (const float*)d_in[7];
    const float* pi_b2  = (const float*)d_in[8];
    const float* dt     = (const float*)d_in[9];
    const float* f_w    = (const float*)d_in[10];
    const float* f_b    = (const float*)d_in[11];
    const float* ln2_g  = (const float*)d_in[12];
    const float* ln2_b  = (const float*)d_in[13];
    float* out = (float*)d_out;

    proj_pi_fw_kernel<<<NTOK/4 + (DDIM/32)*(DDIM/32), 256>>>(
        x, proj_w, proj_b, ln1_g, ln1_b, pi_w1, pi_b1, pi_w2, pi_b2, f_w);
    keps_kernel<<<dim3(32,32), 256>>>();
    gemm_target_kernel<<<dim3(DDIM/64, NTOK/64), 256>>>(f_b);
    gemm_S_kernel<<<dim3(DDIM/64, NTOK/64), 256>>>();
    final_kernel<<<NTOK, 256>>>(x, dt, ln2_g, ln2_b, out);
}

// round 15
// speedup vs baseline: 1.1085x; 1.0466x over previous
#include <cuda_runtime.h>
#include <cuda_fp16.h>
#include <cstdint>

#define NTOK 2048
#define DDIM 768
#define LDIM 16
#define EPSILON_ 0.3f
#define CEXP (1.0f/(4.0f*EPSILON_))

// ---------------- scratch (no allocations allowed) ----------------
__device__ float g_xproj[NTOK*LDIM];
__device__ float g_sqn[NTOK];
__device__ float g_pi[NTOK];
__device__ __half g_kf16[(size_t)NTOK*NTOK];          // 8.4 MB, K_eps fp16
__device__ float g_qpart[NTOK*32];                    // [i][p] transposed partials
__device__ float g_v[NTOK];
__device__ float g_target[NTOK*DDIM];
__device__ float g_S[NTOK*DDIM];
__device__ __half g_x16[NTOK*DDIM];                   // x fp16
__device__ __half g_fwT16[DDIM*DDIM];                 // f_w^T fp16 : [n, k]
__device__ __half g_tv16[NTOK*DDIM];                  // v[m]*target[m,d] fp16, row-major [m][d]

// ---------------- warp-MMA / cp.async helpers (baseline PTX) ----------
__device__ __forceinline__ uint32_t smem_u32(const void* p) {
    uint32_t a;
    asm("{ .reg .u64 t; cvta.to.shared.u64 t, %1; cvt.u32.u64 %0, t; }" : "=r"(a) : "l"(p));
    return a;
}
__device__ __forceinline__ void ldsm_x4(uint32_t* r, uint32_t addr) {
    asm volatile("ldmatrix.sync.aligned.m8n8.x4.shared.b16 {%0,%1,%2,%3}, [%4];"
        : "=r"(r[0]), "=r"(r[1]), "=r"(r[2]), "=r"(r[3]) : "r"(addr));
}
__device__ __forceinline__ void ldsm_x4_trans(uint32_t* r, uint32_t addr) {
    asm volatile("ldmatrix.sync.aligned.m8n8.x4.trans.shared.b16 {%0,%1,%2,%3}, [%4];"
        : "=r"(r[0]), "=r"(r[1]), "=r"(r[2]), "=r"(r[3]) : "r"(addr));
}
__device__ __forceinline__ void mma16816h(float* c, const uint32_t* a, const uint32_t* b) {
    asm volatile("mma.sync.aligned.m16n8k16.row.col.f32.f16.f16.f32 "
        "{%0,%1,%2,%3}, {%4,%5,%6,%7}, {%8,%9}, {%0,%1,%2,%3};"
        : "+f"(c[0]), "+f"(c[1]), "+f"(c[2]), "+f"(c[3])
        : "r"(a[0]), "r"(a[1]), "r"(a[2]), "r"(a[3]), "r"(b[0]), "r"(b[1]));
}
__device__ __forceinline__ void cp16(uint32_t dst, uint64_t gsrc) {
    asm volatile("cp.async.ca.shared.global [%0], [%1], 16;" :: "r"(dst), "l"(gsrc) : "memory");
}
#define CP_COMMIT() asm volatile("cp.async.commit_group;" ::: "memory")
#define CP_WAIT1()  asm volatile("cp.async.wait_group 1;" ::: "memory")
#define CP_WAIT0()  asm volatile("cp.async.wait_group 0;" ::: "memory")

// ---------------- kernel A: proj/LN/ReLU + pi head + x fp16, UNION f_w^T --------
// blocks [0, 512): proj work, 4 rows each.  blocks [512, 1088): f_w transpose.
__global__ __launch_bounds__(256)
void proj_pi_fw_kernel(const float* __restrict__ x, const float* __restrict__ pw,
                       const float* __restrict__ pb, const float* __restrict__ g1,
                       const float* __restrict__ b1, const float* __restrict__ w1,
                       const float* __restrict__ bb1, const float* __restrict__ w2,
                       const float* __restrict__ bb2, const float* __restrict__ fw)
{
    __shared__ float xs[4][DDIM];
    __shared__ float part[256];
    __shared__ float yv[4][LDIM];
    __shared__ float xp[4][LDIM];
    __shared__ float red[4][8];
    __shared__ float tile[32][33];

    const int t = threadIdx.x;

    if (blockIdx.x >= NTOK/4) {
        // ---- f_w transpose block ----
        const int bid = blockIdx.x - NTOK/4;
        const int bx = bid % (DDIM/32), by = bid / (DDIM/32);
        const int r0 = by*32, c0 = bx*32;
        const int tx = t & 31, ty0 = t >> 5;
        #pragma unroll
        for (int p = 0; p < 4; p++) {
            const int ty = ty0 + p*8;
            tile[ty][tx] = fw[(size_t)(r0+ty)*DDIM + c0+tx];
        }
        __syncthreads();
        #pragma unroll
        for (int p = 0; p < 4; p++) {
            const int ty = ty0 + p*8;
            g_fwT16[(size_t)(c0+ty)*DDIM + r0+tx] = __float2half(tile[tx][ty]);
        }
        return;
    }

    // ---- proj / pi block ----
    const int i0 = blockIdx.x * 4;
    const int lane = t & 31, wid = t >> 5;

    #pragma unroll
    for (int r = 0; r < 4; r++)
        for (int d = t; d < DDIM; d += 256) xs[r][d] = x[(size_t)(i0+r)*DDIM + d];
    __syncthreads();

    #pragma unroll
    for (int r = 0; r < 4; r++)
        for (int d = t; d < DDIM; d += 256)
            g_x16[(size_t)(i0+r)*DDIM + d] = __float2half(xs[r][d]);

    const int l = t & 15, g = t >> 4;
    float accs[4] = {};
    for (int d = g; d < DDIM; d += 16) {
        const float w = pw[d*LDIM + l];
        accs[0] += xs[0][d]*w; accs[1] += xs[1][d]*w;
        accs[2] += xs[2][d]*w; accs[3] += xs[3][d]*w;
    }
    #pragma unroll
    for (int r = 0; r < 4; r++) {
        __syncthreads();
        part[t] = accs[r];
        __syncthreads();
        if (t < LDIM) {
            float s = 0.f;
            #pragma unroll
            for (int gg = 0; gg < 16; gg++) s += part[gg*16 + t];
            yv[r][t] = s + pb[t];
        }
    }
    __syncthreads();
    if (t < 4) {
        float mu = 0.f;
        #pragma unroll
        for (int q = 0; q < LDIM; q++) mu += yv[t][q];
        mu *= (1.f/LDIM);
        float var = 0.f;
        #pragma unroll
        for (int q = 0; q < LDIM; q++) { float dd = yv[t][q]-mu; var += dd*dd; }
        var *= (1.f/LDIM);
        const float is = rsqrtf(var + 1e-5f);
        float sq = 0.f;
        #pragma unroll
        for (int q = 0; q < LDIM; q++) {
            float vv = fmaxf((yv[t][q]-mu)*is*g1[q] + b1[q], 0.f);
            xp[t][q] = vv; sq += vv*vv;
        }
        g_sqn[i0+t] = sq;
    }
    __syncthreads();
    if (t < 64) g_xproj[(i0 + (t>>4))*LDIM + (t&15)] = xp[t>>4][t&15];

    float pacc[4] = {};
    for (int dp = t; dp < DDIM; dp += 256) {
        const float bb = bb1[dp], wo = w2[dp];
        float wc[16];
        #pragma unroll
        for (int q = 0; q < 16; q++) wc[q] = w1[q*DDIM + dp];
        #pragma unroll
        for (int r = 0; r < 4; r++) {
            float h = bb;
            #pragma unroll
            for (int q = 0; q < 16; q++) h += xp[r][q]*wc[q];
            h = fmaxf(h, 0.f);
            pacc[r] += h * wo;
        }
    }
    #pragma unroll
    for (int r = 0; r < 4; r++) {
        float v = pacc[r];
        #pragma unroll
        for (int off = 16; off; off >>= 1) v += __shfl_down_sync(0xffffffffu, v, off);
        if (lane == 0) red[r][wid] = v;
    }
    __syncthreads();
    if (t < 4) {
        float s = 0.f;
        #pragma unroll
        for (int q = 0; q < 8; q++) s += red[t][q];
        g_pi[i0+t] = 1.f/(1.f + __expf(-(s + bb2[0])));
    }
}

// ---------------- kernel B: K_eps tile (64x64) -> fp16 + partial rowsums ----
__global__ __launch_bounds__(256)
void keps_kernel()
{
    const int i0 = blockIdx.y * 64, j0 = blockIdx.x * 64;
    const int t = threadIdx.x;
    const int tx = t & 15, ty = t >> 4;
    __shared__ float xi[64][16];
    __shared__ float xjT[16][64];
    __shared__ float si[64], sj[64];
    __shared__ float rs[64][17];
    {
        const int r = t >> 2, c = (t & 3) * 4;
        float4 a = *(const float4*)&g_xproj[(i0 + r)*LDIM + c];
        *(float4*)&xi[r][c] = a;
        float4 b = *(const float4*)&g_xproj[(j0 + r)*LDIM + c];
        xjT[c+0][r] = b.x; xjT[c+1][r] = b.y; xjT[c+2][r] = b.z; xjT[c+3][r] = b.w;
    }
    if (t < 64) { si[t] = g_sqn[i0+t]; sj[t] = g_sqn[j0+t]; }
    __syncthreads();

    float bj[4][16];
    float sjr[4];
    #pragma unroll
    for (int n = 0; n < 4; n++) {
        const int jj = tx*4 + n;
        sjr[n] = sj[jj];
        #pragma unroll
        for (int q = 0; q < 16; q++) bj[n][q] = xjT[q][jj];
    }
    #pragma unroll
    for (int m = 0; m < 4; m++) {
        const int ii = ty*4 + m;
        float a[16];
        #pragma unroll
        for (int q = 0; q < 16; q++) a[q] = xi[ii][q];
        const float sii = si[ii];
        float o[4]; float rsum = 0.f;
        #pragma unroll
        for (int n = 0; n < 4; n++) {
            float dot = 0.f;
            #pragma unroll
            for (int q = 0; q < 16; q++) dot += a[q]*bj[n][q];
            float kv = __expf(-CEXP*(sii + sjr[n] - 2.f*dot));
            o[n] = kv; rsum += kv;
        }
        const size_t base = (size_t)(i0+ii)*NTOK + j0 + tx*4;
        *(__half2*)&g_kf16[base]   = __floats2half2_rn(o[0], o[1]);
        *(__half2*)&g_kf16[base+2] = __floats2half2_rn(o[2], o[3]);
        rs[ii][tx] = rsum;
    }
    __syncthreads();
    if (t < 64) {
        float s = 0.f;
        #pragma unroll
        for (int c = 0; c < 16; c++) s += rs[t][c];
        g_qpart[(i0 + t)*32 + blockIdx.x] = s;   // transposed: contiguous per row
    }
}

// ---------------- unified fp16 2-stage pipelined GEMM, BM=64, 4 warps ----------
// C[2048,768](f32) = A[2048,K] @ B^T (+bias).  A fp16 K-major [m][k].
// TRANSB=false: B fp16 [n][k] (K-major), non-trans ldmatrix.
// TRANSB=true:  B fp16 [k][n] row-major (stride DDIM), trans ldmatrix.
// WRITE_TV: compute v from qpart/pi, also emit g_tv16[m][d]=half(v[m]*C[m][d]).
// BM=64 BN=64 BK=32, 4 warps (2 M x 2 N), warp tile 32x32, double-buffered.
#define GROWB 80                 // bytes per padded A/B(nk) row (32 k * 2B -> 80)
#define BROWB_T 144              // TRANSB B: bytes per padded row (64 n * 2B -> 144)
#define ASTG 5120                // A region = 64*80
template<bool ADD_BIAS, bool TRANSB, bool WRITE_TV>
__device__ __forceinline__
void gemm16_body(const __half* __restrict__ A, const __half* __restrict__ B,
                 const float* __restrict__ bias, float* __restrict__ C, int K)
{
    constexpr uint32_t STG = TRANSB ? (ASTG + 32*BROWB_T)   // 9728
                                    : (ASTG + 64*GROWB);    // 10240
    __shared__ __align__(16) char smem_raw[2*STG];          // <= 20 KB
    __shared__ float vsm[64];
    const uint32_t sbase = smem_u32(smem_raw);
    const int tid = threadIdx.x;
    const int lane = tid & 31, w = tid >> 5;
    const int wm = w & 1, wn = w >> 1;
    const int m0 = blockIdx.y * 64, n0 = blockIdx.x * 64;

    // per-thread cp.async assignments: 512 x 16B per chunk, 4 per thread (128 thr)
    uint64_t srcs[4]; uint32_t dsts[4]; uint64_t advs[4];
    #pragma unroll
    for (int it = 0; it < 4; it++) {
        const int idx = tid + it*128;
        if (idx < 256) {
            const int r = idx >> 2, q = idx & 3;            // 64 rows x 4 x 16B
            srcs[it] = (uint64_t)__cvta_generic_to_global(A + (size_t)(m0+r)*K + q*8);
            dsts[it] = r*GROWB + q*16;
            advs[it] = 64;                                   // 32 k * 2B
        } else if (!TRANSB) {
            const int j = idx - 256;
            const int r = j >> 2, q = j & 3;                 // 64 rows x 4 x 16B
            srcs[it] = (uint64_t)__cvta_generic_to_global(B + (size_t)(n0+r)*K + q*8);
            dsts[it] = ASTG + r*GROWB + q*16;
            advs[it] = 64;
        } else {
            const int j = idx - 256;                         // 0..255
            const int r = j >> 3, q = j & 7;                 // 32 k-rows x 8 x 16B
            srcs[it] = (uint64_t)__cvta_generic_to_global(B + (size_t)r*DDIM + n0 + q*8);
            dsts[it] = ASTG + r*BROWB_T + q*16;
            advs[it] = (uint64_t)32*DDIM*2;                  // advance 32 k-rows
        }
    }

    // A-fragment ldmatrix offsets (bytes, within stage)
    const uint32_t aRow = wm*32 + (lane & 7) + ((lane >> 3) & 1)*8;
    const uint32_t aCol = ((lane >> 4) & 1)*8;
    uint32_t aOff[2];
    #pragma unroll
    for (int mt = 0; mt < 2; mt++) aOff[mt] = (aRow + mt*16)*GROWB + aCol*2;

    // B-fragment ldmatrix offsets: np = 0,1 over warp's 32-col range
    uint32_t bOff[2];
    if (!TRANSB) {
        const uint32_t bRowBase = wn*32 + ((lane >> 4) & 1)*8 + (lane & 7);
        const uint32_t bCol = ((lane >> 3) & 1)*8;
        #pragma unroll
        for (int np = 0; np < 2; np++)
            bOff[np] = ASTG + (bRowBase + np*16)*GROWB + bCol*2;
    } else {
        const uint32_t kRow = (lane & 7) + ((lane >> 3) & 1)*8;
        #pragma unroll
        for (int np = 0; np < 2; np++) {
            const uint32_t nCol = wn*32 + np*16 + ((lane >> 4) & 1)*8;
            bOff[np] = ASTG + kRow*BROWB_T + nCol*2;
        }
    }

    float acc[2][2][2][4] = {};   // [mt][np][j][4]

    // prologue: chunk 0 -> stage 0
    #pragma unroll
    for (int it = 0; it < 4; it++) cp16(sbase + dsts[it], srcs[it]);
    CP_COMMIT();

    // overlap: compute v for this CTA's 64 rows while chunk 0 is in flight
    if (WRITE_TV) {
        #pragma unroll
        for (int i = 0; i < 16; i++) {
            const int r = w*16 + i;
            float q = g_qpart[(m0 + r)*32 + lane];
            #pragma unroll
            for (int off = 16; off; off >>= 1) q += __shfl_xor_sync(0xffffffffu, q, off);
            if (lane == 0) {
                const float vv = g_pi[m0 + r] / q;
                vsm[r] = vv;
                if (blockIdx.x == 0) g_v[m0 + r] = vv;
            }
        }
    }

    const int nch = K >> 5;
    for (int c = 0; c < nch; c++) {
        const uint32_t so = sbase + (uint32_t)(c & 1)*STG;
        if (c + 1 < nch) {
            const uint32_t sn = sbase + (uint32_t)((c+1) & 1)*STG;
            #pragma unroll
            for (int it = 0; it < 4; it++)
                cp16(sn + dsts[it], srcs[it] + (uint64_t)(c+1)*advs[it]);
            CP_COMMIT();
            CP_WAIT1();
        } else {
            CP_WAIT0();
        }
        __syncthreads();

        #pragma unroll
        for (int kk = 0; kk < 2; kk++) {
            uint32_t Af[2][4], Bf[2][4];
            ldsm_x4(Af[0], so + aOff[0] + kk*32);
            ldsm_x4(Af[1], so + aOff[1] + kk*32);
            if (!TRANSB) {
                ldsm_x4(Bf[0], so + bOff[0] + kk*32);
                ldsm_x4(Bf[1], so + bOff[1] + kk*32);
            } else {
                ldsm_x4_trans(Bf[0], so + bOff[0] + kk*16*BROWB_T);
                ldsm_x4_trans(Bf[1], so + bOff[1] + kk*16*BROWB_T);
            }
            #pragma unroll
            for (int mt = 0; mt < 2; mt++)
                #pragma unroll
                for (int np = 0; np < 2; np++) {
                    mma16816h(acc[mt][np][0], Af[mt], &Bf[np][0]);
                    mma16816h(acc[mt][np][1], Af[mt], &Bf[np][2]);
                }
        }
        __syncthreads();
    }

    const int g = lane >> 2, tg2 = (lane & 3)*2;
    #pragma unroll
    for (int mt = 0; mt < 2; mt++) {
        const int r0 = wm*32 + mt*16 + g;
        const int row = m0 + r0;
        float s0 = 0.f, s1 = 0.f;
        if (WRITE_TV) { s0 = vsm[r0]; s1 = vsm[r0 + 8]; }
        #pragma unroll
        for (int np = 0; np < 2; np++)
            #pragma unroll
            for (int j = 0; j < 2; j++) {
                const int col = n0 + wn*32 + np*16 + j*8 + tg2;
                float b0 = 0.f, b1 = 0.f;
                if (ADD_BIAS) { b0 = bias[col]; b1 = bias[col+1]; }
                const float* cc = acc[mt][np][j];
                const float v00 = cc[0]+b0, v01 = cc[1]+b1;
                const float v10 = cc[2]+b0, v11 = cc[3]+b1;
                *(float2*)&C[(size_t)row*DDIM + col] = make_float2(v00, v01);
                *(float2*)&C[(size_t)(row+8)*DDIM + col] = make_float2(v10, v11);
                if (WRITE_TV) {
                    *(__half2*)&g_tv16[(size_t)row*DDIM + col] =
                        __floats2half2_rn(v00*s0, v01*s0);
                    *(__half2*)&g_tv16[(size_t)(row+8)*DDIM + col] =
                        __floats2half2_rn(v10*s1, v11*s1);
                }
            }
    }
}

__global__ __launch_bounds__(128)
void gemm_target_kernel(const float* __restrict__ fb)
{
    gemm16_body<true, false, true>(g_x16, g_fwT16, fb, g_target, DDIM);
}
__global__ __launch_bounds__(128)
void gemm_S_kernel()
{
    gemm16_body<false, true, false>(g_kf16, g_tv16, nullptr, g_S, NTOK);
}

// ---------------- final: d_i + combine + LayerNorm(768) ----------------
__global__ __launch_bounds__(256)
void final_kernel(const float* __restrict__ x, const float* __restrict__ dtp,
                  const float* __restrict__ g2, const float* __restrict__ b2,
                  float* __restrict__ out)
{
    const int i = blockIdx.x;
    const int t = threadIdx.x;
    __shared__ float rsm[256], rqm[256];
    __shared__ float invd_s, mu_s, is_s;

    // fused dvec: d_i = K_eps[i,:] . v + 1e-5
    {
        const __half2* krow = (const __half2*)&g_kf16[(size_t)i*NTOK];
        const int h = t*4;
        __half2 k0 = krow[h], k1 = krow[h+1], k2 = krow[h+2], k3 = krow[h+3];
        float4 v0 = *(const float4*)&g_v[t*8];
        float4 v1 = *(const float4*)&g_v[t*8+4];
        float2 f0 = __half22float2(k0), f1 = __half22float2(k1);
        float2 f2 = __half22float2(k2), f3 = __half22float2(k3);
        rsm[t] = f0.x*v0.x + f0.y*v0.y + f1.x*v0.z + f1.y*v0.w
               + f2.x*v1.x + f2.y*v1.y + f3.x*v1.z + f3.y*v1.w;
    }
    __syncthreads();
    for (int s = 128; s > 0; s >>= 1) {
        if (t < s) rsm[t] += rsm[t+s];
        __syncthreads();
    }
    if (t == 0) invd_s = (1.f/EPSILON_) / (rsm[0] + 1e-5f);
    __syncthreads();

    const float dtv = dtp[0];
    const float invd = invd_s;

    float vals[3];
    float sum = 0.f, sq = 0.f;
    #pragma unroll
    for (int c = 0; c < 3; c++) {
        const int d = t + c*256;
        const float tg = g_target[(size_t)i*DDIM + d];
        const float tt = dtv * (invd * g_S[(size_t)i*DDIM + d] - tg);
        const float t2 = 0.7f * x[(size_t)i*DDIM + d] + 0.3f*(tg + 2.f*tt);
        vals[c] = t2; sum += t2; sq += t2*t2;
    }
    __syncthreads();
    rsm[t] = sum; rqm[t] = sq;
    __syncthreads();
    for (int s = 128; s > 0; s >>= 1) {
        if (t < s) { rsm[t] += rsm[t+s]; rqm[t] += rqm[t+s]; }
        __syncthreads();
    }
    if (t == 0) {
        float mu = rsm[0] * (1.f/DDIM);
        float var = rqm[0] * (1.f/DDIM) - mu*mu;
        mu_s = mu; is_s = rsqrtf(var + 1e-5f);
    }
    __syncthreads();
    #pragma unroll
    for (int c = 0; c < 3; c++) {
        const int d = t + c*256;
        out[(size_t)i*DDIM + d] = (vals[c]-mu_s)*is_s*g2[d] + b2[d];
    }
}

// ---------------- launch (pure kernel launches; nothing else) ----------------
extern "C" void kernel_launch(void* const* d_in, const int* in_sizes, int n_in,
                              void* d_out, int out_size)
{
    const float* x      = (const float*)d_in[0];
    const float* proj_w = (const float*)d_in[1];
    const float* proj_b = (const float*)d_in[2];
    const float* ln1_g  = (const float*)d_in[3];
    const float* ln1_b  = (const float*)d_in[4];
    const float* pi_w1  = (const float*)d_in[5];
    const float* pi_b1  = (const float*)d_in[6];
    const float* pi_w2  = (const float*)d_in[7];
    const float* pi_b2  = (const float*)d_in[8];
    const float* dt     = (const float*)d_in[9];
    const float* f_w    = (const float*)d_in[10];
    const float* f_b    = (const float*)d_in[11];
    const float* ln2_g  = (const float*)d_in[12];
    const float* ln2_b  = (const float*)d_in[13];
    float* out = (float*)d_out;

    proj_pi_fw_kernel<<<NTOK/4 + (DDIM/32)*(DDIM/32), 256>>>(
        x, proj_w, proj_b, ln1_g, ln1_b, pi_w1, pi_b1, pi_w2, pi_b2, f_w);
    keps_kernel<<<dim3(32,32), 256>>>();
    gemm_target_kernel<<<dim3(DDIM/64, NTOK/64), 128>>>(f_b);
    gemm_S_kernel<<<dim3(DDIM/64, NTOK/64), 128>>>();
    final_kernel<<<NTOK, 256>>>(x, dt, ln2_g, ln2_b, out);
}